// round 6
// baseline (speedup 1.0000x reference)
#include <cuda_runtime.h>
#include <cuda_bf16.h>
#include <cuda_fp16.h>

// ---------------------------------------------------------------------------
// NetMHCpan BiLSTM (pep 15 + hla 372 steps, H=1024) + MLP(4096->4096->1)
//
//  K2 lstm: persistent 148-CTA kernel. EACH CTA owns ~7 hidden indices of
//           BOTH directions of the active LSTM (fp16 Whh rows in SMEM,
//           112KB). Per step it alternates: poll-f (warp1) overlapped with
//           gate-b (warp0), compute f rows; gate-f (warp0) overlapped with
//           poll-b (warp2), compute b rows. The cross-SM release->acquire
//           latency of each chain hides behind the other chain's compute.
//           Sync: 16 split counter words per (l,t); producers red.release
//           (no separate membar), consumer warp acquire-polls one/two
//           sectors and sums with __reduce_add_sync.
// ---------------------------------------------------------------------------

#define TMAX   372
#define LP     15
#define H      1024
#define NGATE  4096
#define GRID   148
#define NTHR   256

#define MAXIDX 7            // max hidden indices per CTA per direction
#define MAXROW (MAXIDX*4)   // 28
#define WSTRIDE (MAXROW*1024)              // halves per direction
#define SMEM_BYTES (2*WSTRIDE*2)           // 114688 B fp16 weights (2 dirs)

#define NCW    16           // counter words per (l,t)
#define NCNT   (4 * (TMAX + 1) * NCW)

struct Ptrs {
    const float* x_pep;
    const float* x_hla;
    const float* wih[4];
    const float* whh[4];
    const float* bih[4];
    const float* bhh[4];
    const float* w1;
    const float* b1;
    const float* w2;
    const float* b2;
};

// l: 0=pep_f 1=pep_b 2=hla_f 3=hla_b
__device__ float    g_h[4][TMAX + 1][H];        // hidden states per step
__device__ float    g_xg[4][TMAX][NGATE];       // input projections + biases
__device__ unsigned g_cnt[4][TMAX + 1][NCW];    // split step counters
__device__ float    g_h1[NGATE];                // MLP hidden

__device__ __forceinline__ float sigf(float x) {
    return 1.0f / (1.0f + __expf(-x));
}
__device__ __forceinline__ float tanhf_(float x) {
    float e = __expf(2.0f * x);
    return 1.0f - 2.0f / (e + 1.0f);
}

// ---------------------------------------------------------------- K0: init
__global__ void k_init() {
    int tid = blockIdx.x * blockDim.x + threadIdx.x;
    if (tid < NCNT) {
        // cnt[l][0][*] = 16 (step-0 ready: 2*16*16=512 >= 296), others 0
        int rem = tid % ((TMAX + 1) * NCW);
        ((unsigned*)g_cnt)[tid] = (rem < NCW) ? 16u : 0u;
    }
    if (tid < 4 * H) {
        int l = tid >> 10;
        g_h[l][0][tid & (H - 1)] = 0.0f;
    }
}

// ---------------------------------------------------------------- K1: xg
__global__ void k_xg(Ptrs P) {
    int t = blockIdx.x;
    int l = blockIdx.y;
    int T = (l < 2) ? LP : TMAX;
    if (t >= T) return;
    const float* x = (l < 2) ? P.x_pep : P.x_hla;
    int te = (l & 1) ? (T - 1 - t) : t;      // backward dir: reversed input

    __shared__ float xs[21];
    if (threadIdx.x < 21) xs[threadIdx.x] = x[te * 21 + threadIdx.x];
    __syncthreads();

    const float* wih = P.wih[l];
    const float* ba  = P.bih[l];
    const float* bb  = P.bhh[l];
    for (int r = threadIdx.x; r < NGATE; r += blockDim.x) {
        float a = ba[r] + bb[r];
        const float* w = wih + r * 21;
#pragma unroll
        for (int i = 0; i < 21; i++) a = fmaf(xs[i], w[i], a);
        g_xg[l][t][r] = a;
    }
}

// ---------------------------------------------------------------- helpers
__device__ __forceinline__ void poll_ready(const unsigned* cw, int lane) {
    unsigned s;
    do {
        unsigned v;
        asm volatile("ld.acquire.gpu.u32 %0, [%1];"
                     : "=r"(v) : "l"(cw + (lane & (NCW - 1))) : "memory");
        s = __reduce_add_sync(0xffffffffu, v);   // each word read by 2 lanes
    } while (s < 2u * GRID);                     // 296 when all released
}

__device__ __forceinline__ void dot_rows(const __half* wbase, const float* hsrc_,
                                         float* rowsum, int nrows,
                                         int lane, int warp) {
    const float4* hsrc = (const float4*)hsrc_;
    float4 hA[4], hB[4];
#pragma unroll
    for (int k = 0; k < 4; k++) {
        hA[k] = hsrc[k * 64 + lane * 2];
        hB[k] = hsrc[k * 64 + lane * 2 + 1];
    }
    const uint4* wsu = (const uint4*)wbase;
    for (int r = warp; r < nrows; r += (NTHR / 32)) {
        float a0 = 0.f, a1 = 0.f, a2 = 0.f, a3 = 0.f;
#pragma unroll
        for (int k = 0; k < 4; k++) {
            uint4 w = wsu[r * 128 + k * 32 + lane];
            float2 f;
            f = __half22float2(*(const __half2*)&w.x);
            a0 = fmaf(f.x, hA[k].x, a0); a1 = fmaf(f.y, hA[k].y, a1);
            f = __half22float2(*(const __half2*)&w.y);
            a2 = fmaf(f.x, hA[k].z, a2); a3 = fmaf(f.y, hA[k].w, a3);
            f = __half22float2(*(const __half2*)&w.z);
            a0 = fmaf(f.x, hB[k].x, a0); a1 = fmaf(f.y, hB[k].y, a1);
            f = __half22float2(*(const __half2*)&w.w);
            a2 = fmaf(f.x, hB[k].z, a2); a3 = fmaf(f.y, hB[k].w, a3);
        }
        float a = (a0 + a1) + (a2 + a3);
#pragma unroll
        for (int off = 16; off; off >>= 1)
            a += __shfl_xor_sync(0xffffffffu, a, off);
        if (lane == 0) rowsum[r] = a;
    }
}

// ---------------------------------------------------------------- K2: lstm
__global__ void __launch_bounds__(NTHR, 1) k_lstm(Ptrs P) {
    extern __shared__ __half w_s[];          // [2][28][1024] fp16
    __shared__ float rowsum[2][MAXROW];
    __shared__ float c_s[2][MAXIDX];

    const int tid  = threadIdx.x;
    const int lane = tid & 31;
    const int warp = tid >> 5;
    const int cid  = blockIdx.x;
    const int jb   = (cid * H) / GRID;
    const int je   = ((cid + 1) * H) / GRID;
    const int nidx = je - jb;                // 6 or 7
    const int nrows = nidx * 4;

    for (int phase = 0; phase < 2; phase++) {
        const int lf = phase * 2;            // forward chain id
        const int lb = phase * 2 + 1;        // backward chain id
        const int T  = phase ? TMAX : LP;

        __syncthreads();   // protect w_s / c_s reuse across phases
        // load + convert both directions' weight rows to fp16 SMEM
        for (int d = 0; d < 2; d++) {
            const float4* whh4 = (const float4*)P.whh[lf + d];
            __half2* dstb = (__half2*)(w_s + d * WSTRIDE);
            for (int idx = tid; idx < nrows * 256; idx += NTHR) {
                int r  = idx >> 8;
                int c4 = idx & 255;
                int li = r >> 2, g = r & 3;
                int grow = g * H + jb + li;  // global row in [4096,1024]
                float4 w = whh4[grow * 256 + c4];
                __half2* dst = dstb + r * 512 + c4 * 2;
                dst[0] = __floats2half2_rn(w.x, w.y);
                dst[1] = __floats2half2_rn(w.z, w.w);
            }
        }
        if (tid < 2 * MAXIDX) c_s[tid / MAXIDX][tid % MAXIDX] = 0.0f;
        __syncthreads();

        for (int t = 1; t <= T; t++) {
            // ---- warp0: prefetch xg for both dirs (registers)
            float fxi = 0, fxf = 0, fxg = 0, fxo = 0;
            float bxi = 0, bxf = 0, bxg = 0, bxo = 0;
            if (warp == 0 && lane < nidx) {
                const float* xf = g_xg[lf][t - 1];
                const float* xb = g_xg[lb][t - 1];
                int j = jb + lane;
                fxi = xf[j]; fxf = xf[H + j]; fxg = xf[2 * H + j]; fxo = xf[3 * H + j];
                bxi = xb[j]; bxf = xb[H + j]; bxg = xb[2 * H + j]; bxo = xb[3 * H + j];
            }
            // ---- poll f(t-1)   (overlaps prev iteration's gate-b in warp0)
            if (warp == 1) poll_ready(g_cnt[lf][t - 1], lane);
            __syncthreads();                              // B1

            dot_rows(w_s, g_h[lf][t - 1], rowsum[0], nrows, lane, warp);
            __syncthreads();                              // B2

            // ---- gate f (warp0)  ||  poll b(t-1) (warp2)
            if (warp == 0) {
                if (lane < nidx) {
                    float vi = rowsum[0][lane * 4 + 0] + fxi;
                    float vf = rowsum[0][lane * 4 + 1] + fxf;
                    float vg = rowsum[0][lane * 4 + 2] + fxg;
                    float vo = rowsum[0][lane * 4 + 3] + fxo;
                    float c = sigf(vf) * c_s[0][lane] + sigf(vi) * tanhf_(vg);
                    float h = sigf(vo) * tanhf_(c);
                    c_s[0][lane] = c;
                    g_h[lf][t][jb + lane] = h;
                }
                __syncwarp();
                if (lane == 0)
                    asm volatile("red.release.gpu.global.add.u32 [%0], %1;"
                                 :: "l"(&g_cnt[lf][t][cid & (NCW - 1)]),
                                    "r"(1u) : "memory");
            }
            if (warp == 2) poll_ready(g_cnt[lb][t - 1], lane);
            __syncthreads();                              // B3

            dot_rows(w_s + WSTRIDE, g_h[lb][t - 1], rowsum[1], nrows, lane, warp);
            __syncthreads();                              // B4

            // ---- gate b (warp0); next iter's poll-f overlaps this
            if (warp == 0) {
                if (lane < nidx) {
                    float vi = rowsum[1][lane * 4 + 0] + bxi;
                    float vf = rowsum[1][lane * 4 + 1] + bxf;
                    float vg = rowsum[1][lane * 4 + 2] + bxg;
                    float vo = rowsum[1][lane * 4 + 3] + bxo;
                    float c = sigf(vf) * c_s[1][lane] + sigf(vi) * tanhf_(vg);
                    float h = sigf(vo) * tanhf_(c);
                    c_s[1][lane] = c;
                    g_h[lb][t][jb + lane] = h;
                }
                __syncwarp();
                if (lane == 0)
                    asm volatile("red.release.gpu.global.add.u32 [%0], %1;"
                                 :: "l"(&g_cnt[lb][t][cid & (NCW - 1)]),
                                    "r"(1u) : "memory");
            }
        }
    }
}

// ---------------------------------------------------------------- K3: mlp1
__global__ void k_mlp1(Ptrs P) {
    int row  = blockIdx.x * 8 + (threadIdx.x >> 5);
    int lane = threadIdx.x & 31;
    const float* xseg[4] = { g_h[0][LP], g_h[1][LP], g_h[2][TMAX], g_h[3][TMAX] };
    const float4* w = (const float4*)(P.w1 + row * NGATE);
    float a0 = 0.f, a1 = 0.f, a2 = 0.f, a3 = 0.f;
#pragma unroll
    for (int k = 0; k < 32; k++) {
        int c4  = k * 32 + lane;                  // float4 idx in [0,1024)
        int seg = c4 >> 8;                        // 256 float4 per 1024-seg
        float4 xv = ((const float4*)xseg[seg])[c4 & 255];
        float4 wv = w[c4];
        a0 = fmaf(wv.x, xv.x, a0);
        a1 = fmaf(wv.y, xv.y, a1);
        a2 = fmaf(wv.z, xv.z, a2);
        a3 = fmaf(wv.w, xv.w, a3);
    }
    float a = (a0 + a1) + (a2 + a3);
#pragma unroll
    for (int off = 16; off; off >>= 1) a += __shfl_xor_sync(0xffffffffu, a, off);
    if (lane == 0) g_h1[row] = fmaxf(a + P.b1[row], 0.0f);
}

// ---------------------------------------------------------------- K4: mlp2
__global__ void k_mlp2(Ptrs P, float* out) {
    __shared__ float red[32];
    int tid = threadIdx.x;                         // 1024 threads
    float a = 0.f;
    for (int k = tid; k < NGATE; k += 1024) a = fmaf(g_h1[k], P.w2[k], a);
#pragma unroll
    for (int off = 16; off; off >>= 1) a += __shfl_xor_sync(0xffffffffu, a, off);
    if ((tid & 31) == 0) red[tid >> 5] = a;
    __syncthreads();
    if (tid < 32) {
        float v = red[tid];
#pragma unroll
        for (int off = 16; off; off >>= 1) v += __shfl_xor_sync(0xffffffffu, v, off);
        if (tid == 0) out[0] = v + P.b2[0];
    }
}

// ---------------------------------------------------------------------------
extern "C" void kernel_launch(void* const* d_in, const int* in_sizes, int n_in,
                              void* d_out, int out_size) {
    Ptrs P;
    P.x_pep = (const float*)d_in[0];
    P.x_hla = (const float*)d_in[1];
    // l: 0 pep_f, 1 pep_b, 2 hla_f, 3 hla_b ; groups of (wih, whh, bih, bhh)
    for (int l = 0; l < 4; l++) {
        P.wih[l] = (const float*)d_in[2 + 4 * l + 0];
        P.whh[l] = (const float*)d_in[2 + 4 * l + 1];
        P.bih[l] = (const float*)d_in[2 + 4 * l + 2];
        P.bhh[l] = (const float*)d_in[2 + 4 * l + 3];
    }
    P.w1 = (const float*)d_in[18];
    P.b1 = (const float*)d_in[19];
    P.w2 = (const float*)d_in[20];
    P.b2 = (const float*)d_in[21];

    cudaFuncSetAttribute(k_lstm, cudaFuncAttributeMaxDynamicSharedMemorySize,
                         SMEM_BYTES);

    k_init<<<96, 256>>>();
    dim3 gxg(TMAX, 4);
    k_xg<<<gxg, 256>>>(P);
    k_lstm<<<GRID, NTHR, SMEM_BYTES>>>(P);
    k_mlp1<<<NGATE / 8, 256>>>(P);
    k_mlp2<<<1, 1024>>>(P, (float*)d_out);
}